// round 2
// baseline (speedup 1.0000x reference)
#include <cuda_runtime.h>
#include <cuda_bf16.h>

// ---------------------------------------------------------------------------
// AliasFreeActivation: bias -> up2x(12x12 FIR, pad10, gain4) -> lrelu*sqrt2,
// clamp(+-256) -> 12x12 FIR down2x.
// Input  [8,128,128,128] f32, mid [.,264,264], output [8,128,127,127] f32.
//
// Fully fused, one block = 32x64 output tile of one plane.
// Polyphase up-conv: mid(my,mx) uses 6x6 taps of fu with parity (my&1, mx&1).
// ---------------------------------------------------------------------------

#define H      128
#define W      128
#define OHW    127
#define TY     32
#define TX     64
#define MIDH   74          // 2*TY+10
#define MIDW   138         // 2*TX+10
#define MSTR   148         // mid smem stride (words), 16B-aligned rows
#define INH    43          // TY+11
#define INW    79          // >= TX+11 (=75) + phase-B chunk overrun (needs 78)
#define NTHREADS 256

#define S_IN_OFF   0
#define S_MID_OFF  3400                  // INH*INW=3397 padded to /4
#define S_FU_OFF   (S_MID_OFF + MIDH*MSTR)   // 3400+10952 = 14352
#define S_FD_OFF   (S_FU_OFF + 144)          // 14496
#define SMEM_FLOATS (S_FD_OFF + 144)         // 14640 -> 58560 bytes

__global__ __launch_bounds__(NTHREADS)
void afa_fused_kernel(const float* __restrict__ in,
                      const float* __restrict__ bias,
                      const float* __restrict__ fu,
                      const float* __restrict__ fd,
                      float* __restrict__ out)
{
    extern __shared__ float sm[];
    float* s_in  = sm + S_IN_OFF;
    float* s_mid = sm + S_MID_OFF;
    float* s_fu  = sm + S_FU_OFF;
    float* s_fd  = sm + S_FD_OFF;

    const int tid   = threadIdx.x;
    const int b     = blockIdx.x;
    const int plane = b >> 3;          // n*128 + c
    const int t8    = b & 7;
    const int ty    = t8 >> 1;         // 0..3
    const int tx    = t8 & 1;          // 0..1
    const int oy0   = ty * TY;
    const int ox0   = tx * TX;
    const int iy0   = oy0 - 5;
    const int ix0   = ox0 - 5;

    const float bv = __ldg(&bias[plane & 127]);
    const float* __restrict__ inp = in + (size_t)plane * (H * W);

    // ---- filters into smem (fu pre-scaled by UP*UP = 4) ----
    for (int i = tid; i < 144; i += NTHREADS) {
        s_fu[i] = __ldg(&fu[i]) * 4.0f;
        s_fd[i] = __ldg(&fd[i]);
    }
    // ---- input tile (+bias, zero pad OOB) ----
    for (int i = tid; i < INH * INW; i += NTHREADS) {
        const int r  = i / INW;
        const int cc = i - r * INW;
        const int gy = iy0 + r;
        const int gx = ix0 + cc;
        float v = 0.0f;
        if ((unsigned)gy < (unsigned)H && (unsigned)gx < (unsigned)W)
            v = __ldg(&inp[gy * W + gx]) + bv;
        s_in[i] = v;
    }
    __syncthreads();

    // ---- Phase B: polyphase up-conv + activation into s_mid ----
    // job = (mid row my, 16-wide column chunk). 9 chunks cover 138 (padded 144).
    const float SQ2 = 1.41421356237309515f;
    for (int job = tid; job < MIDH * 9; job += NTHREADS) {
        const int my = job / 9;
        const int c0 = (job - my * 9) << 4;
        const int py = my & 1;
        const int ql = my >> 1;
        const int bic = c0 >> 1;

        float acc[16];
        #pragma unroll
        for (int u = 0; u < 16; u++) acc[u] = 0.0f;

        #pragma unroll 1
        for (int t = 0; t < 6; t++) {
            const float* row = s_in + (ql + t + py) * INW + bic;
            float xv[14];
            #pragma unroll
            for (int j = 0; j < 14; j++) xv[j] = row[j];

            const float4* fr4 = (const float4*)(s_fu + (2 * t + py) * 12);
            float f[12];
            #pragma unroll
            for (int q = 0; q < 3; q++) {
                float4 v4 = fr4[q];
                f[4 * q + 0] = v4.x; f[4 * q + 1] = v4.y;
                f[4 * q + 2] = v4.z; f[4 * q + 3] = v4.w;
            }
            #pragma unroll
            for (int u = 0; u < 16; u++) {
                const int off = (u >> 1) + (u & 1);
                const int pxu = u & 1;
                #pragma unroll
                for (int s = 0; s < 6; s++)
                    acc[u] = fmaf(xv[off + s], f[2 * s + pxu], acc[u]);
            }
        }
        // activation: v*= (already x4 via filter); lrelu * sqrt2; clamp +-256
        #pragma unroll
        for (int u = 0; u < 16; u++) {
            float v = acc[u];
            v = fmaxf(v, 0.2f * v) * SQ2;
            v = fminf(fmaxf(v, -256.0f), 256.0f);
            acc[u] = v;
        }
        float4* ms4 = (float4*)(s_mid + my * MSTR + c0);
        #pragma unroll
        for (int q = 0; q < 4; q++)
            ms4[q] = make_float4(acc[4 * q], acc[4 * q + 1],
                                 acc[4 * q + 2], acc[4 * q + 3]);
    }
    __syncthreads();

    // ---- Phase C: 12x12 down-conv, stride 2 ----
    // thread -> (output row oyl, 8-wide column run)
    const int oyl = tid >> 3;            // 0..31
    const int c0  = (tid & 7) << 3;      // 0,8,...,56

    float acc[8];
    #pragma unroll
    for (int r = 0; r < 8; r++) acc[r] = 0.0f;

    #pragma unroll 1
    for (int ky = 0; ky < 12; ky++) {
        const float* mrow = s_mid + (2 * oyl + ky) * MSTR + 2 * c0;
        float m[26];
        const float4* m4 = (const float4*)mrow;
        #pragma unroll
        for (int q = 0; q < 6; q++) {
            float4 v4 = m4[q];
            m[4 * q + 0] = v4.x; m[4 * q + 1] = v4.y;
            m[4 * q + 2] = v4.z; m[4 * q + 3] = v4.w;
        }
        m[24] = mrow[24];
        m[25] = mrow[25];

        const float4* fr4 = (const float4*)(s_fd + ky * 12);
        float f[12];
        #pragma unroll
        for (int q = 0; q < 3; q++) {
            float4 v4 = fr4[q];
            f[4 * q + 0] = v4.x; f[4 * q + 1] = v4.y;
            f[4 * q + 2] = v4.z; f[4 * q + 3] = v4.w;
        }
        #pragma unroll
        for (int kx = 0; kx < 12; kx++)
            #pragma unroll
            for (int r = 0; r < 8; r++)
                acc[r] = fmaf(f[kx], m[2 * r + kx], acc[r]);
    }

    const int gy = oy0 + oyl;
    if (gy < OHW) {
        const int gx0 = ox0 + c0;
        float* op = out + (size_t)plane * (OHW * OHW) + gy * OHW + gx0;
        #pragma unroll
        for (int r = 0; r < 8; r++)
            if (gx0 + r < OHW) op[r] = acc[r];
    }
}

extern "C" void kernel_launch(void* const* d_in, const int* in_sizes, int n_in,
                              void* d_out, int out_size)
{
    const float* in   = (const float*)d_in[0];
    const float* bias = (const float*)d_in[1];
    const float* fu   = (const float*)d_in[2];
    const float* fd   = (const float*)d_in[3];
    float* out        = (float*)d_out;

    const size_t smem = SMEM_FLOATS * sizeof(float);   // 58560 B
    cudaFuncSetAttribute(afa_fused_kernel,
                         cudaFuncAttributeMaxDynamicSharedMemorySize, (int)smem);

    const int nblocks = 1024 * 8;   // (N*C) planes * (4 y-tiles * 2 x-tiles)
    afa_fused_kernel<<<nblocks, NTHREADS, smem>>>(in, bias, fu, fd, out);
}